// round 13
// baseline (speedup 1.0000x reference)
#include <cuda_runtime.h>
#include <math.h>

// Shapes (fixed by the problem)
#define S_LEN 96
#define B_SZ  32
#define I_DIM 64
#define H_DIM 256
#define M_ALL (S_LEN * B_SZ)      // 3072
#define NELEM (M_ALL * H_DIM)     // 786432 per (S,B,H) slab

typedef unsigned long long u64;

// Scratch (device globals: no allocation allowed in kernel_launch)
__device__ float g_fx[NELEM];   // x @ W_fx^T + b_fx   (S,B,H)
__device__ float g_cx[NELEM];   // x @ W_cx^T + b_cx   (S,B,H)
__device__ float g_hhA[NELEM];  // hh ping
__device__ float g_hhB[NELEM];  // hh pong
__device__ float g_cc[NELEM];   // cell state

// ---------------------------------------------------------------------------
// Packed f32x2 helpers (per-lane RN == scalar FFMA numerics).
// FFMA2 = same MAC/cyc ceiling as scalar FFMA but half the issue slots.
// ---------------------------------------------------------------------------
__device__ __forceinline__ u64 ffma2(u64 a, u64 b, u64 c) {
    u64 d;
    asm("fma.rn.f32x2 %0, %1, %2, %3;" : "=l"(d) : "l"(a), "l"(b), "l"(c));
    return d;
}
__device__ __forceinline__ u64 pack2(float x) {
    u64 r;
    asm("mov.b64 %0, {%1, %1};" : "=l"(r) : "r"(__float_as_uint(x)));
    return r;
}
__device__ __forceinline__ float2 unpack2(u64 v) {
    unsigned lo, hi;
    asm("mov.b64 {%0, %1}, %2;" : "=r"(lo), "=r"(hi) : "l"(v));
    return make_float2(__uint_as_float(lo), __uint_as_float(hi));
}

// Fast transcendentals (abs err ~1e-7; gate is 1e-3 rel on the whole output)
__device__ __forceinline__ float fast_sigmoid(float z) {
    return 1.f / (1.f + __expf(-z));
}
__device__ __forceinline__ float fast_tanh(float x) {
    float e = __expf(2.f * fabsf(x));         // overflow -> inf -> r = 1
    float r = 1.f - __fdividef(2.f, e + 1.f);
    return copysignf(r, x);
}

// ---------------------------------------------------------------------------
// Zero-init: hh(read buffer of step 0) and cc must start at 0 every call.
// ---------------------------------------------------------------------------
__global__ void zero_kernel() {
    int i = blockIdx.x * blockDim.x + threadIdx.x;
    if (i < NELEM / 4) {
        float4 z = make_float4(0.f, 0.f, 0.f, 0.f);
        reinterpret_cast<float4*>(g_hhA)[i] = z;
        reinterpret_cast<float4*>(g_cc)[i]  = z;
    }
}

// ---------------------------------------------------------------------------
// Precompute fx and cx:  (3072 x 64) @ (256 x 64)^T, two weights share x.
// (~1% of runtime; unchanged.)
// ---------------------------------------------------------------------------
__global__ __launch_bounds__(256) void pre_kernel(
    const float* __restrict__ x,
    const float* __restrict__ W_fx, const float* __restrict__ b_fx,
    const float* __restrict__ W_cx, const float* __restrict__ b_cx)
{
    __shared__ __align__(16) float Xs[32][68];
    __shared__ __align__(16) float Wf[32][68];
    __shared__ __align__(16) float Wc[32][68];

    const int tid = threadIdx.x;
    const int bm = blockIdx.x * 64;
    const int bn = blockIdx.y * 64;
    const int m0 = (tid & 15) * 4;
    const int n0 = (tid >> 4) * 4;

    float uf[4][4] = {};
    float uc[4][4] = {};

    for (int c = 0; c < 2; ++c) {
        if (c) __syncthreads();
        const int k0 = c * 32;
        #pragma unroll
        for (int l = 0; l < 2; ++l) {
            int idx = tid + l * 256;
            int row = idx >> 3;
            int seg = idx & 7;
            float4 xa = *reinterpret_cast<const float4*>(&x   [(bm + row) * I_DIM + k0 + seg * 4]);
            float4 wa = *reinterpret_cast<const float4*>(&W_fx[(bn + row) * I_DIM + k0 + seg * 4]);
            float4 wb = *reinterpret_cast<const float4*>(&W_cx[(bn + row) * I_DIM + k0 + seg * 4]);
            int kb = seg * 4;
            Xs[kb+0][row] = xa.x; Xs[kb+1][row] = xa.y; Xs[kb+2][row] = xa.z; Xs[kb+3][row] = xa.w;
            Wf[kb+0][row] = wa.x; Wf[kb+1][row] = wa.y; Wf[kb+2][row] = wa.z; Wf[kb+3][row] = wa.w;
            Wc[kb+0][row] = wb.x; Wc[kb+1][row] = wb.y; Wc[kb+2][row] = wb.z; Wc[kb+3][row] = wb.w;
        }
        __syncthreads();
        #pragma unroll
        for (int kk = 0; kk < 32; ++kk) {
            float a[4], f[4], g[4];
            *reinterpret_cast<float4*>(a) = *reinterpret_cast<const float4*>(&Xs[kk][m0]);
            *reinterpret_cast<float4*>(f) = *reinterpret_cast<const float4*>(&Wf[kk][n0]);
            *reinterpret_cast<float4*>(g) = *reinterpret_cast<const float4*>(&Wc[kk][n0]);
            #pragma unroll
            for (int i = 0; i < 4; ++i)
                #pragma unroll
                for (int j = 0; j < 4; ++j) {
                    uf[i][j] += a[i] * f[j];
                    uc[i][j] += a[i] * g[j];
                }
        }
    }

    float bf[4], bc[4];
    *reinterpret_cast<float4*>(bf) = *reinterpret_cast<const float4*>(&b_fx[bn + n0]);
    *reinterpret_cast<float4*>(bc) = *reinterpret_cast<const float4*>(&b_cx[bn + n0]);
    #pragma unroll
    for (int i = 0; i < 4; ++i) {
        int m = bm + m0 + i;
        float of[4], oc[4];
        #pragma unroll
        for (int j = 0; j < 4; ++j) {
            of[j] = uf[i][j] + bf[j];
            oc[j] = uc[i][j] + bc[j];
        }
        *reinterpret_cast<float4*>(&g_fx[m * H_DIM + bn + n0]) = *reinterpret_cast<float4*>(of);
        *reinterpret_cast<float4*>(&g_cx[m * H_DIM + bn + n0]) = *reinterpret_cast<float4*>(oc);
    }
}

// ---------------------------------------------------------------------------
// One recurrence step (launched 96x).
// Tile 64(M) x 32(N), 256 threads (8 warps -> 20.8 warps/SM at 384 CTAs),
// per-thread micro-tile 2M x (4+4)N, packed FFMA2 accumulators.
//   tx = tid&31 -> m = bm + 2*tx + {0,1}   (LDS.64 on A, conflict-free)
//   ty = tid>>5 -> n0 = ty*4               (B reads broadcast within warp)
// A staged transposed [k][m] pitch 66; B staged [k][n] pitch 36 (16B rows).
// K=256 in 16-chunks, double-buffered smem.
// ---------------------------------------------------------------------------
#define ROWA 66
#define ROWB 36

__global__ __launch_bounds__(256) void step_kernel(
    const float* __restrict__ W_fh, const float* __restrict__ b_fh,
    const float* __restrict__ W_ch, const float* __restrict__ b_ch,
    float* __restrict__ out, int t)
{
    __shared__ __align__(16) float As[2][16][ROWA];
    __shared__ __align__(16) float Bs[2][2][16][ROWB];   // [buf][f/c][k][n]

    const float* __restrict__ hin  = (t & 1) ? g_hhB : g_hhA;
    float*       __restrict__ hout = (t & 1) ? g_hhA : g_hhB;

    const int tid = threadIdx.x;
    const int bm = blockIdx.x * 64;
    const int bn = blockIdx.y * 32;
    const int tx = tid & 31;          // m pair: m = 2*tx + i
    const int n0 = (tid >> 5) * 4;    // 0..28 (per-warp constant -> broadcast)

    // staging indices
    const int arow = tid >> 2;        // 0..63 (A rows)
    const int aseg = tid & 3;         // k group of 4
    const int brow = tid & 31;        // 0..31 (B rows)
    const int bseg = (tid >> 5) & 3;  // k group of 4
    const int bsel = tid >> 7;        // 0: W_fh, 1: W_ch
    const float* __restrict__ Wb = bsel ? W_ch : W_fh;

    // accumulators: u2[i][jp] = (u[2tx+i][n0+2jp], u[2tx+i][n0+2jp+1])
    u64 u2[2][2] = {};
    u64 v2[2][2] = {};

    float4 ra, rb;

    // ---- prologue: load + stage chunk 0 ----
    ra = *reinterpret_cast<const float4*>(&hin[(bm + arow) * H_DIM + aseg * 4]);
    rb = *reinterpret_cast<const float4*>(&Wb [(bn + brow) * H_DIM + bseg * 4]);
    {
        int ka = aseg * 4;
        As[0][ka+0][arow] = ra.x; As[0][ka+1][arow] = ra.y;
        As[0][ka+2][arow] = ra.z; As[0][ka+3][arow] = ra.w;
        int kb = bseg * 4;
        Bs[0][bsel][kb+0][brow] = rb.x; Bs[0][bsel][kb+1][brow] = rb.y;
        Bs[0][bsel][kb+2][brow] = rb.z; Bs[0][bsel][kb+3][brow] = rb.w;
    }
    __syncthreads();

    #pragma unroll 1
    for (int c = 0; c < 16; ++c) {
        const int p = c & 1;
        if (c < 15) {
            const int k0 = (c + 1) * 16;
            ra = *reinterpret_cast<const float4*>(&hin[(bm + arow) * H_DIM + k0 + aseg * 4]);
            rb = *reinterpret_cast<const float4*>(&Wb [(bn + brow) * H_DIM + k0 + bseg * 4]);
        }
        #pragma unroll
        for (int kk = 0; kk < 16; ++kk) {
            float2 a = *reinterpret_cast<const float2*>(&As[p][kk][2 * tx]);
            ulonglong2 ff = *reinterpret_cast<const ulonglong2*>(&Bs[p][0][kk][n0]);
            ulonglong2 gg = *reinterpret_cast<const ulonglong2*>(&Bs[p][1][kk][n0]);
            u64 a0 = pack2(a.x);
            u64 a1 = pack2(a.y);
            u2[0][0] = ffma2(a0, ff.x, u2[0][0]);
            u2[0][1] = ffma2(a0, ff.y, u2[0][1]);
            v2[0][0] = ffma2(a0, gg.x, v2[0][0]);
            v2[0][1] = ffma2(a0, gg.y, v2[0][1]);
            u2[1][0] = ffma2(a1, ff.x, u2[1][0]);
            u2[1][1] = ffma2(a1, ff.y, u2[1][1]);
            v2[1][0] = ffma2(a1, gg.x, v2[1][0]);
            v2[1][1] = ffma2(a1, gg.y, v2[1][1]);
        }
        if (c < 15) {
            const int q = (c + 1) & 1;
            int ka = aseg * 4;
            As[q][ka+0][arow] = ra.x; As[q][ka+1][arow] = ra.y;
            As[q][ka+2][arow] = ra.z; As[q][ka+3][arow] = ra.w;
            int kb = bseg * 4;
            Bs[q][bsel][kb+0][brow] = rb.x; Bs[q][bsel][kb+1][brow] = rb.y;
            Bs[q][bsel][kb+2][brow] = rb.z; Bs[q][bsel][kb+3][brow] = rb.w;
        }
        __syncthreads();
    }

    // ---- fused gate epilogue ----
    float bfh[4], bch[4];
    *reinterpret_cast<float4*>(bfh) = *reinterpret_cast<const float4*>(&b_fh[bn + n0]);
    *reinterpret_cast<float4*>(bch) = *reinterpret_cast<const float4*>(&b_ch[bn + n0]);

    float* hseq = out + (size_t)t * NELEM;
    const int last = (t == S_LEN - 1);

    #pragma unroll
    for (int i = 0; i < 2; ++i) {
        const int m  = bm + 2 * tx + i;
        const int bb = m & (B_SZ - 1);          // batch index (m = s*B + b)
        const int off = m * H_DIM + bn + n0;

        float fx4[4], cx4[4], cc4[4];
        *reinterpret_cast<float4*>(fx4) = *reinterpret_cast<const float4*>(&g_fx[(t * B_SZ + bb) * H_DIM + bn + n0]);
        *reinterpret_cast<float4*>(cx4) = *reinterpret_cast<const float4*>(&g_cx[off]);
        *reinterpret_cast<float4*>(cc4) = *reinterpret_cast<const float4*>(&g_cc[off]);

        float2 u01 = unpack2(u2[i][0]);
        float2 u23 = unpack2(u2[i][1]);
        float2 v01 = unpack2(v2[i][0]);
        float2 v23 = unpack2(v2[i][1]);
        float uu[4] = {u01.x, u01.y, u23.x, u23.y};
        float vv[4] = {v01.x, v01.y, v23.x, v23.y};

        float hn[4], cn[4];
        #pragma unroll
        for (int j = 0; j < 4; ++j) {
            float gate = fast_sigmoid(fx4[j] + uu[j] + bfh[j]);
            float cand = fast_tanh(cx4[j] + vv[j] + bch[j]);
            float c2   = gate * (cc4[j] + cand);   // forget gate == input gate (ref bug)
            cn[j] = c2;
            hn[j] = gate * fast_tanh(c2);          // output gate == g (ref bug)
        }
        *reinterpret_cast<float4*>(&g_cc[off]) = *reinterpret_cast<float4*>(cn);
        *reinterpret_cast<float4*>(&hout[off]) = *reinterpret_cast<float4*>(hn);
        *reinterpret_cast<float4*>(&hseq[off]) = *reinterpret_cast<float4*>(hn);
        if (last) {
            *reinterpret_cast<float4*>(&out[(size_t)S_LEN * NELEM + off])       = *reinterpret_cast<float4*>(hn);
            *reinterpret_cast<float4*>(&out[(size_t)(S_LEN + 1) * NELEM + off]) = *reinterpret_cast<float4*>(cn);
        }
    }
}

// ---------------------------------------------------------------------------
// Launch: init -> input projections -> 96 sequential fused steps.
// Inputs (metadata order): x, W_fx, b_fx, W_fh, b_fh, W_cx, b_cx, W_ch, b_ch
// Output: [h_seq (S,S,B,H) | h_fin (S,B,H) | c_fin (S,B,H)] flattened.
// ---------------------------------------------------------------------------
extern "C" void kernel_launch(void* const* d_in, const int* in_sizes, int n_in,
                              void* d_out, int out_size)
{
    const float* x    = (const float*)d_in[0];
    const float* W_fx = (const float*)d_in[1];
    const float* b_fx = (const float*)d_in[2];
    const float* W_fh = (const float*)d_in[3];
    const float* b_fh = (const float*)d_in[4];
    const float* W_cx = (const float*)d_in[5];
    const float* b_cx = (const float*)d_in[6];
    const float* W_ch = (const float*)d_in[7];
    const float* b_ch = (const float*)d_in[8];
    float* out = (float*)d_out;

    zero_kernel<<<(NELEM / 4 + 255) / 256, 256>>>();
    pre_kernel<<<dim3(M_ALL / 64, H_DIM / 64), 256>>>(x, W_fx, b_fx, W_cx, b_cx);

    dim3 grid(M_ALL / 64, H_DIM / 32);   // 48 x 8 = 384 CTAs
    for (int t = 0; t < S_LEN; ++t) {
        step_kernel<<<grid, 256>>>(W_fh, b_fh, W_ch, b_ch, out, t);
    }
}

// round 15
// speedup vs baseline: 1.7814x; 1.7814x over previous
#include <cuda_runtime.h>
#include <cuda_bf16.h>
#include <cstdint>
#include <math.h>

// Shapes (fixed by the problem)
#define S_LEN 96
#define B_SZ  32
#define I_DIM 64
#define H_DIM 256
#define M_ALL (S_LEN * B_SZ)      // 3072
#define NELEM (M_ALL * H_DIM)     // 786432

typedef unsigned long long u64;
typedef unsigned int u32;

// ---------------------------------------------------------------------------
// Scratch (device globals: no allocation allowed)
// ---------------------------------------------------------------------------
__device__ float g_fx[NELEM];                 // x@W_fx^T + b_fx + b_fh
__device__ float g_cx[NELEM];                 // x@W_cx^T + b_cx + b_ch
__device__ float g_cc[NELEM];                 // cell state
__device__ __nv_bfloat16 g_hhi[2][NELEM];     // hh hi (bf16), ping-pong
__device__ __nv_bfloat16 g_hlo[2][NELEM];     // hh lo (bf16), ping-pong
__device__ __nv_bfloat16 g_Wfhi[H_DIM * H_DIM];
__device__ __nv_bfloat16 g_Wflo[H_DIM * H_DIM];
__device__ __nv_bfloat16 g_Wchi[H_DIM * H_DIM];
__device__ __nv_bfloat16 g_Wclo[H_DIM * H_DIM];

// ---------------------------------------------------------------------------
// Generic-PTX helpers (NO tcgen05 — harness compiles for plain compute_103)
// ---------------------------------------------------------------------------
__device__ __forceinline__ u32 smem_to_u32(const void* p) {
    u32 a;
    asm("{ .reg .u64 t; cvta.to.shared.u64 t, %1; cvt.u32.u64 %0, t; }" : "=r"(a) : "l"(p));
    return a;
}
__device__ __forceinline__ void ldsm_x4(u32& r0, u32& r1, u32& r2, u32& r3, u32 addr) {
    asm volatile("ldmatrix.sync.aligned.m8n8.x4.shared.b16 {%0,%1,%2,%3}, [%4];"
                 : "=r"(r0), "=r"(r1), "=r"(r2), "=r"(r3) : "r"(addr));
}
__device__ __forceinline__ void mma_bf16(float* d, const u32* a, const u32* b) {
    asm volatile(
        "mma.sync.aligned.m16n8k16.row.col.f32.bf16.bf16.f32 "
        "{%0,%1,%2,%3}, {%4,%5,%6,%7}, {%8,%9}, {%0,%1,%2,%3};"
        : "+f"(d[0]), "+f"(d[1]), "+f"(d[2]), "+f"(d[3])
        : "r"(a[0]), "r"(a[1]), "r"(a[2]), "r"(a[3]), "r"(b[0]), "r"(b[1]));
}
#define CP_ASYNC16(smem, gmem) \
    asm volatile("cp.async.ca.shared.global [%0], [%1], 16;" :: "r"((u32)(smem)), "l"(gmem))
#define CP_COMMIT() asm volatile("cp.async.commit_group;" ::: "memory")
#define CP_WAIT(n)  asm volatile("cp.async.wait_group %0;" :: "n"(n) : "memory")

// Fast transcendentals (validated rel_err 1.39e-7 in R5-R13 epilogues)
__device__ __forceinline__ float fast_sigmoid(float z) {
    return 1.f / (1.f + __expf(-z));
}
__device__ __forceinline__ float fast_tanh(float x) {
    float e = __expf(2.f * fabsf(x));
    float r = 1.f - __fdividef(2.f, e + 1.f);
    return copysignf(r, x);
}

// ---------------------------------------------------------------------------
// Init kernels
// ---------------------------------------------------------------------------
__global__ void zero_kernel() {
    int i = blockIdx.x * blockDim.x + threadIdx.x;
    if (i < NELEM / 4) {
        float4 z = make_float4(0.f, 0.f, 0.f, 0.f);
        reinterpret_cast<float4*>(g_cc)[i] = z;
    }
    if (i < NELEM / 8) {
        uint4 z4 = make_uint4(0, 0, 0, 0);
        reinterpret_cast<uint4*>(g_hhi[0])[i] = z4;
        reinterpret_cast<uint4*>(g_hlo[0])[i] = z4;
    }
}

__global__ void splitw_kernel(const float* __restrict__ Wf,
                              const float* __restrict__ Wc) {
    int i = blockIdx.x * blockDim.x + threadIdx.x;
    if (i < H_DIM * H_DIM) {
        float wf = Wf[i];
        __nv_bfloat16 h = __float2bfloat16(wf);
        g_Wfhi[i] = h;
        g_Wflo[i] = __float2bfloat16(wf - __bfloat162float(h));
        float wc = Wc[i];
        h = __float2bfloat16(wc);
        g_Wchi[i] = h;
        g_Wclo[i] = __float2bfloat16(wc - __bfloat162float(h));
    }
}

// ---------------------------------------------------------------------------
// Precompute fx,cx (with b_fh/b_ch folded in):  (3072x64)@(256x64)^T
// ---------------------------------------------------------------------------
__global__ __launch_bounds__(256) void pre_kernel(
    const float* __restrict__ x,
    const float* __restrict__ W_fx, const float* __restrict__ b_fx,
    const float* __restrict__ W_cx, const float* __restrict__ b_cx,
    const float* __restrict__ b_fh, const float* __restrict__ b_ch)
{
    __shared__ __align__(16) float Xs[32][68];
    __shared__ __align__(16) float Wf[32][68];
    __shared__ __align__(16) float Wc[32][68];

    const int tid = threadIdx.x;
    const int bm = blockIdx.x * 64;
    const int bn = blockIdx.y * 64;
    const int m0 = (tid & 15) * 4;
    const int n0 = (tid >> 4) * 4;

    float uf[4][4] = {};
    float uc[4][4] = {};

    for (int c = 0; c < 2; ++c) {
        if (c) __syncthreads();
        const int k0 = c * 32;
        #pragma unroll
        for (int l = 0; l < 2; ++l) {
            int idx = tid + l * 256;
            int row = idx >> 3;
            int seg = idx & 7;
            float4 xa = *reinterpret_cast<const float4*>(&x   [(bm + row) * I_DIM + k0 + seg * 4]);
            float4 wa = *reinterpret_cast<const float4*>(&W_fx[(bn + row) * I_DIM + k0 + seg * 4]);
            float4 wb = *reinterpret_cast<const float4*>(&W_cx[(bn + row) * I_DIM + k0 + seg * 4]);
            int kb = seg * 4;
            Xs[kb+0][row] = xa.x; Xs[kb+1][row] = xa.y; Xs[kb+2][row] = xa.z; Xs[kb+3][row] = xa.w;
            Wf[kb+0][row] = wa.x; Wf[kb+1][row] = wa.y; Wf[kb+2][row] = wa.z; Wf[kb+3][row] = wa.w;
            Wc[kb+0][row] = wb.x; Wc[kb+1][row] = wb.y; Wc[kb+2][row] = wb.z; Wc[kb+3][row] = wb.w;
        }
        __syncthreads();
        #pragma unroll
        for (int kk = 0; kk < 32; ++kk) {
            float a[4], f[4], g[4];
            *reinterpret_cast<float4*>(a) = *reinterpret_cast<const float4*>(&Xs[kk][m0]);
            *reinterpret_cast<float4*>(f) = *reinterpret_cast<const float4*>(&Wf[kk][n0]);
            *reinterpret_cast<float4*>(g) = *reinterpret_cast<const float4*>(&Wc[kk][n0]);
            #pragma unroll
            for (int i = 0; i < 4; ++i)
                #pragma unroll
                for (int j = 0; j < 4; ++j) {
                    uf[i][j] += a[i] * f[j];
                    uc[i][j] += a[i] * g[j];
                }
        }
    }

    #pragma unroll
    for (int i = 0; i < 4; ++i) {
        int m = bm + m0 + i;
        float of[4], oc[4];
        #pragma unroll
        for (int j = 0; j < 4; ++j) {
            of[j] = uf[i][j] + b_fx[bn + n0 + j] + b_fh[bn + n0 + j];
            oc[j] = uc[i][j] + b_cx[bn + n0 + j] + b_ch[bn + n0 + j];
        }
        *reinterpret_cast<float4*>(&g_fx[m * H_DIM + bn + n0]) = *reinterpret_cast<float4*>(of);
        *reinterpret_cast<float4*>(&g_cx[m * H_DIM + bn + n0]) = *reinterpret_cast<float4*>(oc);
    }
}

// ---------------------------------------------------------------------------
// Tensor-core recurrence step via warp-level mma.sync (generic PTX, sm_80+).
// CTA: 128M x 64N of BOTH U=hh@W_fh^T and V=hh@W_ch^T; K=256.
// bf16x3 fp32 emulation: U += Ahi*Bhi + Ahi*Blo + Alo*Bhi, f32 accumulate.
// 8 warps, warp tile 32M x 32N (2 m16 x 4 n8 per gemm).
// Weights (4 split matrices, 64x256) staged once in smem; hh streamed in
// 4 K-chunks of 64 with cp.async double buffering.
// Grid (24, 4) = 96 CTAs -> single wave.
// ---------------------------------------------------------------------------
#define W_STRIDE 528                 // 264 bf16 per row (4-bank rotation)
#define A_STRIDE 144                 // 72 bf16 per row
#define SW_SZ (64 * W_STRIDE)        // 33792 B per weight matrix
#define OFF_A (4 * SW_SZ)            // 135168
#define SA_SZ (128 * A_STRIDE)       // 18432 B per (buf, half)
#define SMEM_TOTAL (OFF_A + 4 * SA_SZ)   // 208896 B

__global__ __launch_bounds__(256, 1)
void step_tc(float* __restrict__ out, int t)
{
    extern __shared__ __align__(16) char smem[];
    const u32 sbase = smem_to_u32(smem);

    const int tid = threadIdx.x;
    const int lane = tid & 31;
    const int wid = tid >> 5;
    const int bm = blockIdx.x * 128;
    const int bn = blockIdx.y * 64;
    const int wm = (wid & 3) * 32;        // warp M offset in tile
    const int wn = (wid >> 2) * 32;       // warp N offset in tile

    const __nv_bfloat16* __restrict__ hin_hi = g_hhi[t & 1];
    const __nv_bfloat16* __restrict__ hin_lo = g_hlo[t & 1];
    __nv_bfloat16* __restrict__ hout_hi = g_hhi[(t & 1) ^ 1];
    __nv_bfloat16* __restrict__ hout_lo = g_hlo[(t & 1) ^ 1];

    // ---- stage weights (once) + A chunk 0, A chunk 1 via cp.async ----
    {
        const __nv_bfloat16* wsrc[4] = {g_Wfhi, g_Wflo, g_Wchi, g_Wclo};
        #pragma unroll
        for (int mat = 0; mat < 4; ++mat) {
            #pragma unroll
            for (int i = 0; i < 8; ++i) {
                int idx = tid + 256 * i;
                int n = idx >> 5, k = (idx & 31) * 8;
                CP_ASYNC16(sbase + mat * SW_SZ + n * W_STRIDE + k * 2,
                           &wsrc[mat][(bn + n) * H_DIM + k]);
            }
        }
        // A chunk 0 into buf 0
        #pragma unroll
        for (int i = 0; i < 4; ++i) {
            int idx = tid + 256 * i;
            int row = idx >> 3, seg = idx & 7;
            CP_ASYNC16(sbase + OFF_A + 0 * SA_SZ + row * A_STRIDE + seg * 16,
                       &hin_hi[(bm + row) * H_DIM + seg * 8]);
            CP_ASYNC16(sbase + OFF_A + 1 * SA_SZ + row * A_STRIDE + seg * 16,
                       &hin_lo[(bm + row) * H_DIM + seg * 8]);
        }
        CP_COMMIT();
        // A chunk 1 into buf 1
        #pragma unroll
        for (int i = 0; i < 4; ++i) {
            int idx = tid + 256 * i;
            int row = idx >> 3, seg = idx & 7;
            CP_ASYNC16(sbase + OFF_A + 2 * SA_SZ + row * A_STRIDE + seg * 16,
                       &hin_hi[(bm + row) * H_DIM + 64 + seg * 8]);
            CP_ASYNC16(sbase + OFF_A + 3 * SA_SZ + row * A_STRIDE + seg * 16,
                       &hin_lo[(bm + row) * H_DIM + 64 + seg * 8]);
        }
        CP_COMMIT();
    }

    // accumulators: [m16 tile][n8 tile][4 f32]
    float u[2][4][4] = {};
    float v[2][4][4] = {};

    // ldmatrix lane address components (8x8 quad layout)
    const int lr = (lane & 7) + 8 * ((lane >> 3) & 1);   // row within 16
    const int lk = 8 * (lane >> 4);                       // k offset (0 or 8)

    // A base addresses (per buf/half), row part
    const u32 aAddrBase = sbase + OFF_A + (wm + lr) * A_STRIDE + lk * 2;
    // B base addresses per matrix: rows = n
    const u32 bRow = (wn + lr) * W_STRIDE + lk * 2;

    #pragma unroll 1
    for (int c = 0; c < 4; ++c) {
        const int buf = c & 1;
        if (c < 3) CP_WAIT(1); else CP_WAIT(0);
        __syncthreads();   // staged data visible to all warps

        const u32 aHi = aAddrBase + (buf * 2 + 0) * SA_SZ;
        const u32 aLo = aAddrBase + (buf * 2 + 1) * SA_SZ;
        const u32 kByteW = (c * 64) * 2;   // weight k offset for this chunk

        #pragma unroll
        for (int ks = 0; ks < 4; ++ks) {
            u32 ahi[2][4], alo[2][4];
            #pragma unroll
            for (int mi = 0; mi < 2; ++mi) {
                ldsm_x4(ahi[mi][0], ahi[mi][1], ahi[mi][2], ahi[mi][3],
                        aHi + mi * 16 * A_STRIDE + ks * 32);
                ldsm_x4(alo[mi][0], alo[mi][1], alo[mi][2], alo[mi][3],
                        aLo + mi * 16 * A_STRIDE + ks * 32);
            }
            // B fragments: [matrix][n8 tile][2]
            u32 bf_h[4][2], bf_l[4][2], bc_h[4][2], bc_l[4][2];
            #pragma unroll
            for (int nh = 0; nh < 2; ++nh) {
                u32 off = bRow + nh * 16 * W_STRIDE + kByteW + ks * 32;
                u32 r0, r1, r2, r3;
                ldsm_x4(r0, r1, r2, r3, sbase + 0 * SW_SZ + off);
                bf_h[nh*2][0] = r0; bf_h[nh*2][1] = r2; bf_h[nh*2+1][0] = r1; bf_h[nh*2+1][1] = r3;
                ldsm_x4(r0, r1, r2, r3, sbase + 1 * SW_SZ + off);
                bf_l[nh*2][0] = r0; bf_l[nh*2][1] = r2; bf_l[nh*2+1][0] = r1; bf_l[nh*2+1][1] = r3;
                ldsm_x4(r0, r1, r2, r3, sbase + 2 * SW_SZ + off);
                bc_h[nh*2][0] = r0; bc_h[nh*2][1] = r2; bc_h[nh*2+1][0] = r1; bc_h[nh*2+1][1] = r3;
                ldsm_x4(r0, r1, r2, r3, sbase + 3 * SW_SZ + off);
                bc_l[nh*2][0] = r0; bc_l[nh*2][1] = r2; bc_l[nh*2+1][0] = r1; bc_l[nh*2+1][1] = r3;
            }
            #pragma unroll
            for (int mi = 0; mi < 2; ++mi)
                #pragma unroll
                for (int nj = 0; nj < 4; ++nj) {
                    mma_bf16(u[mi][nj], ahi[mi], bf_h[nj]);
                    mma_bf16(u[mi][nj], ahi[mi], bf_l[nj]);
                    mma_bf16(u[mi][nj], alo[mi], bf_h[nj]);
                    mma_bf16(v[mi][nj], ahi[mi], bc_h[nj]);
                    mma_bf16(v[mi][nj], ahi[mi], bc_l[nj]);
                    mma_bf16(v[mi][nj], alo[mi], bc_h[nj]);
                }
        }

        __syncthreads();   // all warps done reading buffer `buf`
        if (c + 2 <= 3) {  // refill this buffer with chunk c+2
            const int kc = (c + 2) * 64;
            #pragma unroll
            for (int i = 0; i < 4; ++i) {
                int idx = tid + 256 * i;
                int row = idx >> 3, seg = idx & 7;
                CP_ASYNC16(sbase + OFF_A + (buf * 2 + 0) * SA_SZ + row * A_STRIDE + seg * 16,
                           &hin_hi[(bm + row) * H_DIM + kc + seg * 8]);
                CP_ASYNC16(sbase + OFF_A + (buf * 2 + 1) * SA_SZ + row * A_STRIDE + seg * 16,
                           &hin_lo[(bm + row) * H_DIM + kc + seg * 8]);
            }
            CP_COMMIT();
        }
    }

    // ---- fused gate epilogue (register accumulators -> gmem) ----
    const int gid = lane >> 2;
    const int tig = lane & 3;
    float* hseq = out + (size_t)t * NELEM;
    const int last = (t == S_LEN - 1);

    #pragma unroll
    for (int mi = 0; mi < 2; ++mi) {
        #pragma unroll
        for (int half = 0; half < 2; ++half) {
            const int r = bm + wm + mi * 16 + gid + half * 8;
            const int bb = r & (B_SZ - 1);
            #pragma unroll
            for (int nj = 0; nj < 4; ++nj) {
                const int col = bn + wn + nj * 8 + 2 * tig;
                const int off = r * H_DIM + col;

                float u0 = u[mi][nj][half * 2 + 0], u1 = u[mi][nj][half * 2 + 1];
                float v0 = v[mi][nj][half * 2 + 0], v1 = v[mi][nj][half * 2 + 1];

                float2 fx2 = *reinterpret_cast<const float2*>(&g_fx[(t * B_SZ + bb) * H_DIM + col]);
                float2 cx2 = *reinterpret_cast<const float2*>(&g_cx[off]);
                float2 cc2 = *reinterpret_cast<const float2*>(&g_cc[off]);

                float g0 = fast_sigmoid(fx2.x + u0);
                float g1 = fast_sigmoid(fx2.y + u1);
                float d0 = fast_tanh(cx2.x + v0);
                float d1 = fast_tanh(cx2.y + v1);
                float c0 = g0 * (cc2.x + d0);        // forget==input gate (ref bug)
                float c1 = g1 * (cc2.y + d1);
                float h0 = g0 * fast_tanh(c0);       // output gate == g (ref bug)
                float h1 = g1 * fast_tanh(c1);

                *reinterpret_cast<float2*>(&g_cc[off]) = make_float2(c0, c1);
                *reinterpret_cast<float2*>(&hseq[off]) = make_float2(h0, h1);

                __nv_bfloat16 h0h = __float2bfloat16(h0);
                __nv_bfloat16 h1h = __float2bfloat16(h1);
                __nv_bfloat162 hi2, lo2;
                hi2.x = h0h; hi2.y = h1h;
                lo2.x = __float2bfloat16(h0 - __bfloat162float(h0h));
                lo2.y = __float2bfloat16(h1 - __bfloat162float(h1h));
                *reinterpret_cast<__nv_bfloat162*>(&hout_hi[off]) = hi2;
                *reinterpret_cast<__nv_bfloat162*>(&hout_lo[off]) = lo2;

                if (last) {
                    *reinterpret_cast<float2*>(&out[(size_t)S_LEN * NELEM + off])       = make_float2(h0, h1);
                    *reinterpret_cast<float2*>(&out[(size_t)(S_LEN + 1) * NELEM + off]) = make_float2(c0, c1);
                }
            }
        }
    }
}

// ---------------------------------------------------------------------------
// Launch: init -> weight split -> input projections -> 96 mma.sync steps.
// Inputs: x, W_fx, b_fx, W_fh, b_fh, W_cx, b_cx, W_ch, b_ch
// Output: [h_seq (S,S,B,H) | h_fin (S,B,H) | c_fin (S,B,H)]
// ---------------------------------------------------------------------------
extern "C" void kernel_launch(void* const* d_in, const int* in_sizes, int n_in,
                              void* d_out, int out_size)
{
    const float* x    = (const float*)d_in[0];
    const float* W_fx = (const float*)d_in[1];
    const float* b_fx = (const float*)d_in[2];
    const float* W_fh = (const float*)d_in[3];
    const float* b_fh = (const float*)d_in[4];
    const float* W_cx = (const float*)d_in[5];
    const float* b_cx = (const float*)d_in[6];
    const float* W_ch = (const float*)d_in[7];
    const float* b_ch = (const float*)d_in[8];
    float* out = (float*)d_out;

    static bool attr_set = false;
    if (!attr_set) {
        cudaFuncSetAttribute(step_tc, cudaFuncAttributeMaxDynamicSharedMemorySize, SMEM_TOTAL);
        attr_set = true;
    }

    zero_kernel<<<(NELEM / 4 + 255) / 256, 256>>>();
    splitw_kernel<<<(H_DIM * H_DIM + 255) / 256, 256>>>(W_fh, W_ch);
    pre_kernel<<<dim3(M_ALL / 64, H_DIM / 64), 256>>>(x, W_fx, b_fx, W_cx, b_cx, b_fh, b_ch);

    dim3 grid(M_ALL / 128, H_DIM / 64);   // 24 x 4 = 96 CTAs, single wave
    for (int t = 0; t < S_LEN; ++t) {
        step_tc<<<grid, 256, SMEM_TOTAL>>>(out, t);
    }
}

// round 16
// speedup vs baseline: 1.8586x; 1.0433x over previous
#include <cuda_runtime.h>
#include <cuda_bf16.h>
#include <cstdint>
#include <math.h>

// Shapes (fixed by the problem)
#define S_LEN 96
#define B_SZ  32
#define I_DIM 64
#define H_DIM 256
#define M_ALL (S_LEN * B_SZ)      // 3072
#define NELEM (M_ALL * H_DIM)     // 786432
#define NCTA  96                  // persistent grid (24 x 4)

typedef unsigned long long u64;
typedef unsigned int u32;

// ---------------------------------------------------------------------------
// Scratch (device globals: no allocation allowed)
// ---------------------------------------------------------------------------
__device__ float g_fx[NELEM];                 // x@W_fx^T + b_fx + b_fh
__device__ float g_cx[NELEM];                 // x@W_cx^T + b_cx + b_ch
__device__ float g_cc[NELEM];                 // cell state
__device__ __nv_bfloat16 g_hhi[2][NELEM];     // hh hi (bf16), ping-pong
__device__ __nv_bfloat16 g_hlo[2][NELEM];     // hh lo (bf16), ping-pong
__device__ __nv_bfloat16 g_Wfhi[H_DIM * H_DIM];
__device__ __nv_bfloat16 g_Wflo[H_DIM * H_DIM];
__device__ __nv_bfloat16 g_Wchi[H_DIM * H_DIM];
__device__ __nv_bfloat16 g_Wclo[H_DIM * H_DIM];
__device__ unsigned g_bar;                    // grid-barrier arrival counter

// ---------------------------------------------------------------------------
// Generic-PTX helpers (NO tcgen05 — harness compiles for plain compute_103)
// ---------------------------------------------------------------------------
__device__ __forceinline__ u32 smem_to_u32(const void* p) {
    u32 a;
    asm("{ .reg .u64 t; cvta.to.shared.u64 t, %1; cvt.u32.u64 %0, t; }" : "=r"(a) : "l"(p));
    return a;
}
__device__ __forceinline__ void ldsm_x4(u32& r0, u32& r1, u32& r2, u32& r3, u32 addr) {
    asm volatile("ldmatrix.sync.aligned.m8n8.x4.shared.b16 {%0,%1,%2,%3}, [%4];"
                 : "=r"(r0), "=r"(r1), "=r"(r2), "=r"(r3) : "r"(addr));
}
__device__ __forceinline__ void mma_bf16(float* d, const u32* a, const u32* b) {
    asm volatile(
        "mma.sync.aligned.m16n8k16.row.col.f32.bf16.bf16.f32 "
        "{%0,%1,%2,%3}, {%4,%5,%6,%7}, {%8,%9}, {%0,%1,%2,%3};"
        : "+f"(d[0]), "+f"(d[1]), "+f"(d[2]), "+f"(d[3])
        : "r"(a[0]), "r"(a[1]), "r"(a[2]), "r"(a[3]), "r"(b[0]), "r"(b[1]));
}
// .ca: cache in L1 (read-once-per-kernel weights).
#define CP_ASYNC_CA(smem, gmem) \
    asm volatile("cp.async.ca.shared.global [%0], [%1], 16;" :: "r"((u32)(smem)), "l"(gmem))
// .cg: L2 only — REQUIRED for hh inside the persistent loop (L1 not coherent
// across CTAs and never flushed during the kernel).
#define CP_ASYNC_CG(smem, gmem) \
    asm volatile("cp.async.cg.shared.global [%0], [%1], 16;" :: "r"((u32)(smem)), "l"(gmem))
#define CP_COMMIT() asm volatile("cp.async.commit_group;" ::: "memory")
#define CP_WAIT(n)  asm volatile("cp.async.wait_group %0;" :: "n"(n) : "memory")

// Fast transcendentals (validated: rel_err 1.7e-6 end-to-end in R14)
__device__ __forceinline__ float fast_sigmoid(float z) {
    return 1.f / (1.f + __expf(-z));
}
__device__ __forceinline__ float fast_tanh(float x) {
    float e = __expf(2.f * fabsf(x));
    float r = 1.f - __fdividef(2.f, e + 1.f);
    return copysignf(r, x);
}

// ---------------------------------------------------------------------------
// Init kernels
// ---------------------------------------------------------------------------
__global__ void zero_kernel() {
    int i = blockIdx.x * blockDim.x + threadIdx.x;
    if (i == 0) g_bar = 0;                     // reset grid barrier each launch
    if (i < NELEM / 4) {
        float4 z = make_float4(0.f, 0.f, 0.f, 0.f);
        reinterpret_cast<float4*>(g_cc)[i] = z;
    }
    if (i < NELEM / 8) {
        uint4 z4 = make_uint4(0, 0, 0, 0);
        reinterpret_cast<uint4*>(g_hhi[0])[i] = z4;
        reinterpret_cast<uint4*>(g_hlo[0])[i] = z4;
    }
}

__global__ void splitw_kernel(const float* __restrict__ Wf,
                              const float* __restrict__ Wc) {
    int i = blockIdx.x * blockDim.x + threadIdx.x;
    if (i < H_DIM * H_DIM) {
        float wf = Wf[i];
        __nv_bfloat16 h = __float2bfloat16(wf);
        g_Wfhi[i] = h;
        g_Wflo[i] = __float2bfloat16(wf - __bfloat162float(h));
        float wc = Wc[i];
        h = __float2bfloat16(wc);
        g_Wchi[i] = h;
        g_Wclo[i] = __float2bfloat16(wc - __bfloat162float(h));
    }
}

// ---------------------------------------------------------------------------
// Precompute fx,cx (with b_fh/b_ch folded in):  (3072x64)@(256x64)^T
// ---------------------------------------------------------------------------
__global__ __launch_bounds__(256) void pre_kernel(
    const float* __restrict__ x,
    const float* __restrict__ W_fx, const float* __restrict__ b_fx,
    const float* __restrict__ W_cx, const float* __restrict__ b_cx,
    const float* __restrict__ b_fh, const float* __restrict__ b_ch)
{
    __shared__ __align__(16) float Xs[32][68];
    __shared__ __align__(16) float Wf[32][68];
    __shared__ __align__(16) float Wc[32][68];

    const int tid = threadIdx.x;
    const int bm = blockIdx.x * 64;
    const int bn = blockIdx.y * 64;
    const int m0 = (tid & 15) * 4;
    const int n0 = (tid >> 4) * 4;

    float uf[4][4] = {};
    float uc[4][4] = {};

    for (int c = 0; c < 2; ++c) {
        if (c) __syncthreads();
        const int k0 = c * 32;
        #pragma unroll
        for (int l = 0; l < 2; ++l) {
            int idx = tid + l * 256;
            int row = idx >> 3;
            int seg = idx & 7;
            float4 xa = *reinterpret_cast<const float4*>(&x   [(bm + row) * I_DIM + k0 + seg * 4]);
            float4 wa = *reinterpret_cast<const float4*>(&W_fx[(bn + row) * I_DIM + k0 + seg * 4]);
            float4 wb = *reinterpret_cast<const float4*>(&W_cx[(bn + row) * I_DIM + k0 + seg * 4]);
            int kb = seg * 4;
            Xs[kb+0][row] = xa.x; Xs[kb+1][row] = xa.y; Xs[kb+2][row] = xa.z; Xs[kb+3][row] = xa.w;
            Wf[kb+0][row] = wa.x; Wf[kb+1][row] = wa.y; Wf[kb+2][row] = wa.z; Wf[kb+3][row] = wa.w;
            Wc[kb+0][row] = wb.x; Wc[kb+1][row] = wb.y; Wc[kb+2][row] = wb.z; Wc[kb+3][row] = wb.w;
        }
        __syncthreads();
        #pragma unroll
        for (int kk = 0; kk < 32; ++kk) {
            float a[4], f[4], g[4];
            *reinterpret_cast<float4*>(a) = *reinterpret_cast<const float4*>(&Xs[kk][m0]);
            *reinterpret_cast<float4*>(f) = *reinterpret_cast<const float4*>(&Wf[kk][n0]);
            *reinterpret_cast<float4*>(g) = *reinterpret_cast<const float4*>(&Wc[kk][n0]);
            #pragma unroll
            for (int i = 0; i < 4; ++i)
                #pragma unroll
                for (int j = 0; j < 4; ++j) {
                    uf[i][j] += a[i] * f[j];
                    uc[i][j] += a[i] * g[j];
                }
        }
    }

    #pragma unroll
    for (int i = 0; i < 4; ++i) {
        int m = bm + m0 + i;
        float of[4], oc[4];
        #pragma unroll
        for (int j = 0; j < 4; ++j) {
            of[j] = uf[i][j] + b_fx[bn + n0 + j] + b_fh[bn + n0 + j];
            oc[j] = uc[i][j] + b_cx[bn + n0 + j] + b_ch[bn + n0 + j];
        }
        *reinterpret_cast<float4*>(&g_fx[m * H_DIM + bn + n0]) = *reinterpret_cast<float4*>(of);
        *reinterpret_cast<float4*>(&g_cx[m * H_DIM + bn + n0]) = *reinterpret_cast<float4*>(oc);
    }
}

// ---------------------------------------------------------------------------
// PERSISTENT tensor-core recurrence: one launch, 96 CTAs (24x4), weights in
// smem ONCE, 96 timesteps inside the kernel with a grid barrier per step.
// Per step & CTA: 128M x 64N of U=hh@W_fh^T and V=hh@W_ch^T, K=256 in 4
// cp.async.cg double-buffered chunks; bf16x3 fp32 emulation
// (Ahi*Bhi + Ahi*Blo + Alo*Bhi, f32 accumulate); fused gate epilogue.
// ---------------------------------------------------------------------------
#define W_STRIDE 528                 // 264 bf16 per row
#define A_STRIDE 144                 // 72 bf16 per row
#define SW_SZ (64 * W_STRIDE)        // 33792 B per weight matrix
#define OFF_A (4 * SW_SZ)            // 135168
#define SA_SZ (128 * A_STRIDE)       // 18432 B per (buf, half)
#define SMEM_TOTAL (OFF_A + 4 * SA_SZ)   // 208896 B

__global__ __launch_bounds__(256, 1)
void lstm_persist(float* __restrict__ out)
{
    extern __shared__ __align__(16) char smem[];
    const u32 sbase = smem_to_u32(smem);

    const int tid = threadIdx.x;
    const int lane = tid & 31;
    const int wid = tid >> 5;
    const int bm = blockIdx.x * 128;
    const int bn = blockIdx.y * 64;
    const int wm = (wid & 3) * 32;
    const int wn = (wid >> 2) * 32;

    // ---- stage weights ONCE (.ca — read-only for whole kernel) ----
    {
        const __nv_bfloat16* wsrc[4] = {g_Wfhi, g_Wflo, g_Wchi, g_Wclo};
        #pragma unroll
        for (int mat = 0; mat < 4; ++mat) {
            #pragma unroll
            for (int i = 0; i < 8; ++i) {
                int idx = tid + 256 * i;
                int n = idx >> 5, k = (idx & 31) * 8;
                CP_ASYNC_CA(sbase + mat * SW_SZ + n * W_STRIDE + k * 2,
                            &wsrc[mat][(bn + n) * H_DIM + k]);
            }
        }
        CP_COMMIT();
    }

    // ldmatrix lane address components
    const int lr = (lane & 7) + 8 * ((lane >> 3) & 1);
    const int lk = 8 * (lane >> 4);
    const u32 aAddrBase = sbase + OFF_A + (wm + lr) * A_STRIDE + lk * 2;
    const u32 bRow = (wn + lr) * W_STRIDE + lk * 2;

    const int gid = lane >> 2;
    const int tig = lane & 3;

    #pragma unroll 1
    for (int t = 0; t < S_LEN; ++t) {
        const __nv_bfloat16* __restrict__ hin_hi = g_hhi[t & 1];
        const __nv_bfloat16* __restrict__ hin_lo = g_hlo[t & 1];
        __nv_bfloat16* __restrict__ hout_hi = g_hhi[(t & 1) ^ 1];
        __nv_bfloat16* __restrict__ hout_lo = g_hlo[(t & 1) ^ 1];

        // ---- stage A chunks 0,1 (.cg: hh written by other CTAs last step) ----
        #pragma unroll
        for (int i = 0; i < 4; ++i) {
            int idx = tid + 256 * i;
            int row = idx >> 3, seg = idx & 7;
            CP_ASYNC_CG(sbase + OFF_A + 0 * SA_SZ + row * A_STRIDE + seg * 16,
                        &hin_hi[(bm + row) * H_DIM + seg * 8]);
            CP_ASYNC_CG(sbase + OFF_A + 1 * SA_SZ + row * A_STRIDE + seg * 16,
                        &hin_lo[(bm + row) * H_DIM + seg * 8]);
        }
        CP_COMMIT();
        #pragma unroll
        for (int i = 0; i < 4; ++i) {
            int idx = tid + 256 * i;
            int row = idx >> 3, seg = idx & 7;
            CP_ASYNC_CG(sbase + OFF_A + 2 * SA_SZ + row * A_STRIDE + seg * 16,
                        &hin_hi[(bm + row) * H_DIM + 64 + seg * 8]);
            CP_ASYNC_CG(sbase + OFF_A + 3 * SA_SZ + row * A_STRIDE + seg * 16,
                        &hin_lo[(bm + row) * H_DIM + 64 + seg * 8]);
        }
        CP_COMMIT();

        float u[2][4][4] = {};
        float v[2][4][4] = {};

        #pragma unroll 1
        for (int c = 0; c < 4; ++c) {
            const int buf = c & 1;
            if (c < 3) CP_WAIT(1); else CP_WAIT(0);
            __syncthreads();

            const u32 aHi = aAddrBase + (buf * 2 + 0) * SA_SZ;
            const u32 aLo = aAddrBase + (buf * 2 + 1) * SA_SZ;
            const u32 kByteW = (c * 64) * 2;

            #pragma unroll
            for (int ks = 0; ks < 4; ++ks) {
                u32 ahi[2][4], alo[2][4];
                #pragma unroll
                for (int mi = 0; mi < 2; ++mi) {
                    ldsm_x4(ahi[mi][0], ahi[mi][1], ahi[mi][2], ahi[mi][3],
                            aHi + mi * 16 * A_STRIDE + ks * 32);
                    ldsm_x4(alo[mi][0], alo[mi][1], alo[mi][2], alo[mi][3],
                            aLo + mi * 16 * A_STRIDE + ks * 32);
                }
                u32 bf_h[4][2], bf_l[4][2], bc_h[4][2], bc_l[4][2];
                #pragma unroll
                for (int nh = 0; nh < 2; ++nh) {
                    u32 off = bRow + nh * 16 * W_STRIDE + kByteW + ks * 32;
                    u32 r0, r1, r2, r3;
                    ldsm_x4(r0, r1, r2, r3, sbase + 0 * SW_SZ + off);
                    bf_h[nh*2][0] = r0; bf_h[nh*2][1] = r2; bf_h[nh*2+1][0] = r1; bf_h[nh*2+1][1] = r3;
                    ldsm_x4(r0, r1, r2, r3, sbase + 1 * SW_SZ + off);
                    bf_l[nh*2][0] = r0; bf_l[nh*2][1] = r2; bf_l[nh*2+1][0] = r1; bf_l[nh*2+1][1] = r3;
                    ldsm_x4(r0, r1, r2, r3, sbase + 2 * SW_SZ + off);
                    bc_h[nh*2][0] = r0; bc_h[nh*2][1] = r2; bc_h[nh*2+1][0] = r1; bc_h[nh*2+1][1] = r3;
                    ldsm_x4(r0, r1, r2, r3, sbase + 3 * SW_SZ + off);
                    bc_l[nh*2][0] = r0; bc_l[nh*2][1] = r2; bc_l[nh*2+1][0] = r1; bc_l[nh*2+1][1] = r3;
                }
                #pragma unroll
                for (int mi = 0; mi < 2; ++mi)
                    #pragma unroll
                    for (int nj = 0; nj < 4; ++nj) {
                        mma_bf16(u[mi][nj], ahi[mi], bf_h[nj]);
                        mma_bf16(u[mi][nj], ahi[mi], bf_l[nj]);
                        mma_bf16(u[mi][nj], alo[mi], bf_h[nj]);
                        mma_bf16(v[mi][nj], ahi[mi], bc_h[nj]);
                        mma_bf16(v[mi][nj], ahi[mi], bc_l[nj]);
                        mma_bf16(v[mi][nj], alo[mi], bc_h[nj]);
                    }
            }

            __syncthreads();
            if (c + 2 <= 3) {
                const int kc = (c + 2) * 64;
                #pragma unroll
                for (int i = 0; i < 4; ++i) {
                    int idx = tid + 256 * i;
                    int row = idx >> 3, seg = idx & 7;
                    CP_ASYNC_CG(sbase + OFF_A + (buf * 2 + 0) * SA_SZ + row * A_STRIDE + seg * 16,
                                &hin_hi[(bm + row) * H_DIM + kc + seg * 8]);
                    CP_ASYNC_CG(sbase + OFF_A + (buf * 2 + 1) * SA_SZ + row * A_STRIDE + seg * 16,
                                &hin_lo[(bm + row) * H_DIM + kc + seg * 8]);
                }
                CP_COMMIT();
            }
        }

        // ---- fused gate epilogue ----
        float* hseq = out + (size_t)t * NELEM;
        const int last = (t == S_LEN - 1);

        #pragma unroll
        for (int mi = 0; mi < 2; ++mi) {
            #pragma unroll
            for (int half = 0; half < 2; ++half) {
                const int r = bm + wm + mi * 16 + gid + half * 8;
                const int bb = r & (B_SZ - 1);
                #pragma unroll
                for (int nj = 0; nj < 4; ++nj) {
                    const int col = bn + wn + nj * 8 + 2 * tig;
                    const int off = r * H_DIM + col;

                    float u0 = u[mi][nj][half * 2 + 0], u1 = u[mi][nj][half * 2 + 1];
                    float v0 = v[mi][nj][half * 2 + 0], v1 = v[mi][nj][half * 2 + 1];

                    float2 fx2 = *reinterpret_cast<const float2*>(&g_fx[(t * B_SZ + bb) * H_DIM + col]);
                    float2 cx2 = *reinterpret_cast<const float2*>(&g_cx[off]);
                    float2 cc2 = *reinterpret_cast<const float2*>(&g_cc[off]);

                    float g0 = fast_sigmoid(fx2.x + u0);
                    float g1 = fast_sigmoid(fx2.y + u1);
                    float d0 = fast_tanh(cx2.x + v0);
                    float d1 = fast_tanh(cx2.y + v1);
                    float c0 = g0 * (cc2.x + d0);        // forget==input gate (ref bug)
                    float c1 = g1 * (cc2.y + d1);
                    float h0 = g0 * fast_tanh(c0);       // output gate == g (ref bug)
                    float h1 = g1 * fast_tanh(c1);

                    *reinterpret_cast<float2*>(&g_cc[off]) = make_float2(c0, c1);
                    *reinterpret_cast<float2*>(&hseq[off]) = make_float2(h0, h1);

                    __nv_bfloat16 h0h = __float2bfloat16(h0);
                    __nv_bfloat16 h1h = __float2bfloat16(h1);
                    __nv_bfloat162 hi2, lo2;
                    hi2.x = h0h; hi2.y = h1h;
                    lo2.x = __float2bfloat16(h0 - __bfloat162float(h0h));
                    lo2.y = __float2bfloat16(h1 - __bfloat162float(h1h));
                    *reinterpret_cast<__nv_bfloat162*>(&hout_hi[off]) = hi2;
                    *reinterpret_cast<__nv_bfloat162*>(&hout_lo[off]) = lo2;

                    if (last) {
                        *reinterpret_cast<float2*>(&out[(size_t)S_LEN * NELEM + off])       = make_float2(h0, h1);
                        *reinterpret_cast<float2*>(&out[(size_t)(S_LEN + 1) * NELEM + off]) = make_float2(c0, c1);
                    }
                }
            }
        }

        // ---- grid barrier (skip after last step) ----
        if (t < S_LEN - 1) {
            __threadfence();          // make hout stores visible (L2)
            __syncthreads();          // all threads of CTA fenced
            if (tid == 0) {
                atomicAdd(&g_bar, 1u);
                const unsigned goal = (unsigned)NCTA * (unsigned)(t + 1);
                while (*((volatile unsigned*)&g_bar) < goal) {
                    __nanosleep(64);
                }
            }
            __syncthreads();
            __threadfence();          // acquire side
        }
    }
}

// ---------------------------------------------------------------------------
// Launch: init -> weight split -> input projections -> ONE persistent kernel.
// Inputs: x, W_fx, b_fx, W_fh, b_fh, W_cx, b_cx, W_ch, b_ch
// Output: [h_seq (S,S,B,H) | h_fin (S,B,H) | c_fin (S,B,H)]
// ---------------------------------------------------------------------------
extern "C" void kernel_launch(void* const* d_in, const int* in_sizes, int n_in,
                              void* d_out, int out_size)
{
    const float* x    = (const float*)d_in[0];
    const float* W_fx = (const float*)d_in[1];
    const float* b_fx = (const float*)d_in[2];
    const float* W_fh = (const float*)d_in[3];
    const float* b_fh = (const float*)d_in[4];
    const float* W_cx = (const float*)d_in[5];
    const float* b_cx = (const float*)d_in[6];
    const float* W_ch = (const float*)d_in[7];
    const float* b_ch = (const float*)d_in[8];
    float* out = (float*)d_out;

    cudaFuncSetAttribute(lstm_persist, cudaFuncAttributeMaxDynamicSharedMemorySize, SMEM_TOTAL);

    zero_kernel<<<(NELEM / 4 + 255) / 256, 256>>>();
    splitw_kernel<<<(H_DIM * H_DIM + 255) / 256, 256>>>(W_fh, W_ch);
    pre_kernel<<<dim3(M_ALL / 64, H_DIM / 64), 256>>>(x, W_fx, b_fx, W_cx, b_cx, b_fh, b_ch);

    dim3 grid(M_ALL / 128, H_DIM / 64);   // 24 x 4 = 96 CTAs, all co-resident
    lstm_persist<<<grid, 256, SMEM_TOTAL>>>(out);
}

// round 17
// speedup vs baseline: 1.8653x; 1.0036x over previous
#include <cuda_runtime.h>
#include <cuda_bf16.h>
#include <cstdint>
#include <math.h>

// Shapes (fixed by the problem)
#define S_LEN 96
#define B_SZ  32
#define I_DIM 64
#define H_DIM 256
#define M_ALL (S_LEN * B_SZ)      // 3072
#define NELEM (M_ALL * H_DIM)     // 786432
#define NCTA  96                  // persistent grid (24 x 4)

typedef unsigned long long u64;
typedef unsigned int u32;

// ---------------------------------------------------------------------------
// Scratch (device globals: no allocation allowed)
// ---------------------------------------------------------------------------
__device__ float g_fx[NELEM];                 // x@W_fx^T + b_fx + b_fh
__device__ float g_cx[NELEM];                 // x@W_cx^T + b_cx + b_ch
__device__ float g_cc[NELEM];                 // cell state
__device__ __nv_bfloat16 g_hhi[2][NELEM];     // hh hi (bf16), ping-pong
__device__ __nv_bfloat16 g_hlo[2][NELEM];     // hh lo (bf16), ping-pong
__device__ __nv_bfloat16 g_Wfhi[H_DIM * H_DIM];
__device__ __nv_bfloat16 g_Wflo[H_DIM * H_DIM];
__device__ __nv_bfloat16 g_Wchi[H_DIM * H_DIM];
__device__ __nv_bfloat16 g_Wclo[H_DIM * H_DIM];
__device__ unsigned g_bar;                    // grid-barrier arrival counter

// ---------------------------------------------------------------------------
// Generic-PTX helpers (NO tcgen05 — harness compiles for plain compute_103)
// ---------------------------------------------------------------------------
__device__ __forceinline__ u32 smem_to_u32(const void* p) {
    u32 a;
    asm("{ .reg .u64 t; cvta.to.shared.u64 t, %1; cvt.u32.u64 %0, t; }" : "=r"(a) : "l"(p));
    return a;
}
__device__ __forceinline__ void ldsm_x4(u32& r0, u32& r1, u32& r2, u32& r3, u32 addr) {
    asm volatile("ldmatrix.sync.aligned.m8n8.x4.shared.b16 {%0,%1,%2,%3}, [%4];"
                 : "=r"(r0), "=r"(r1), "=r"(r2), "=r"(r3) : "r"(addr));
}
__device__ __forceinline__ void mma_bf16(float* d, const u32* a, const u32* b) {
    asm volatile(
        "mma.sync.aligned.m16n8k16.row.col.f32.bf16.bf16.f32 "
        "{%0,%1,%2,%3}, {%4,%5,%6,%7}, {%8,%9}, {%0,%1,%2,%3};"
        : "+f"(d[0]), "+f"(d[1]), "+f"(d[2]), "+f"(d[3])
        : "r"(a[0]), "r"(a[1]), "r"(a[2]), "r"(a[3]), "r"(b[0]), "r"(b[1]));
}
// .ca: cache in L1 (read-once-per-kernel weights).
#define CP_ASYNC_CA(smem, gmem) \
    asm volatile("cp.async.ca.shared.global [%0], [%1], 16;" :: "r"((u32)(smem)), "l"(gmem))
// .cg: L2 only — REQUIRED for hh inside the persistent loop (L1 not coherent
// across CTAs and never flushed during the kernel).
#define CP_ASYNC_CG(smem, gmem) \
    asm volatile("cp.async.cg.shared.global [%0], [%1], 16;" :: "r"((u32)(smem)), "l"(gmem))
#define CP_COMMIT() asm volatile("cp.async.commit_group;" ::: "memory")
#define CP_WAIT(n)  asm volatile("cp.async.wait_group %0;" :: "n"(n) : "memory")

// Fast transcendentals (validated: rel_err 1.7e-6 end-to-end in R14)
__device__ __forceinline__ float fast_sigmoid(float z) {
    return 1.f / (1.f + __expf(-z));
}
__device__ __forceinline__ float fast_tanh(float x) {
    float e = __expf(2.f * fabsf(x));
    float r = 1.f - __fdividef(2.f, e + 1.f);
    return copysignf(r, x);
}

// ---------------------------------------------------------------------------
// Init kernels
// ---------------------------------------------------------------------------
__global__ void zero_kernel() {
    int i = blockIdx.x * blockDim.x + threadIdx.x;
    if (i == 0) g_bar = 0;                     // reset grid barrier each launch
    if (i < NELEM / 4) {
        float4 z = make_float4(0.f, 0.f, 0.f, 0.f);
        reinterpret_cast<float4*>(g_cc)[i] = z;
    }
    if (i < NELEM / 8) {
        uint4 z4 = make_uint4(0, 0, 0, 0);
        reinterpret_cast<uint4*>(g_hhi[0])[i] = z4;
        reinterpret_cast<uint4*>(g_hlo[0])[i] = z4;
    }
}

__global__ void splitw_kernel(const float* __restrict__ Wf,
                              const float* __restrict__ Wc) {
    int i = blockIdx.x * blockDim.x + threadIdx.x;
    if (i < H_DIM * H_DIM) {
        float wf = Wf[i];
        __nv_bfloat16 h = __float2bfloat16(wf);
        g_Wfhi[i] = h;
        g_Wflo[i] = __float2bfloat16(wf - __bfloat162float(h));
        float wc = Wc[i];
        h = __float2bfloat16(wc);
        g_Wchi[i] = h;
        g_Wclo[i] = __float2bfloat16(wc - __bfloat162float(h));
    }
}

// ---------------------------------------------------------------------------
// Precompute fx,cx (with b_fh/b_ch folded in):  (3072x64)@(256x64)^T
// ---------------------------------------------------------------------------
__global__ __launch_bounds__(256) void pre_kernel(
    const float* __restrict__ x,
    const float* __restrict__ W_fx, const float* __restrict__ b_fx,
    const float* __restrict__ W_cx, const float* __restrict__ b_cx,
    const float* __restrict__ b_fh, const float* __restrict__ b_ch)
{
    __shared__ __align__(16) float Xs[32][68];
    __shared__ __align__(16) float Wf[32][68];
    __shared__ __align__(16) float Wc[32][68];

    const int tid = threadIdx.x;
    const int bm = blockIdx.x * 64;
    const int bn = blockIdx.y * 64;
    const int m0 = (tid & 15) * 4;
    const int n0 = (tid >> 4) * 4;

    float uf[4][4] = {};
    float uc[4][4] = {};

    for (int c = 0; c < 2; ++c) {
        if (c) __syncthreads();
        const int k0 = c * 32;
        #pragma unroll
        for (int l = 0; l < 2; ++l) {
            int idx = tid + l * 256;
            int row = idx >> 3;
            int seg = idx & 7;
            float4 xa = *reinterpret_cast<const float4*>(&x   [(bm + row) * I_DIM + k0 + seg * 4]);
            float4 wa = *reinterpret_cast<const float4*>(&W_fx[(bn + row) * I_DIM + k0 + seg * 4]);
            float4 wb = *reinterpret_cast<const float4*>(&W_cx[(bn + row) * I_DIM + k0 + seg * 4]);
            int kb = seg * 4;
            Xs[kb+0][row] = xa.x; Xs[kb+1][row] = xa.y; Xs[kb+2][row] = xa.z; Xs[kb+3][row] = xa.w;
            Wf[kb+0][row] = wa.x; Wf[kb+1][row] = wa.y; Wf[kb+2][row] = wa.z; Wf[kb+3][row] = wa.w;
            Wc[kb+0][row] = wb.x; Wc[kb+1][row] = wb.y; Wc[kb+2][row] = wb.z; Wc[kb+3][row] = wb.w;
        }
        __syncthreads();
        #pragma unroll
        for (int kk = 0; kk < 32; ++kk) {
            float a[4], f[4], g[4];
            *reinterpret_cast<float4*>(a) = *reinterpret_cast<const float4*>(&Xs[kk][m0]);
            *reinterpret_cast<float4*>(f) = *reinterpret_cast<const float4*>(&Wf[kk][n0]);
            *reinterpret_cast<float4*>(g) = *reinterpret_cast<const float4*>(&Wc[kk][n0]);
            #pragma unroll
            for (int i = 0; i < 4; ++i)
                #pragma unroll
                for (int j = 0; j < 4; ++j) {
                    uf[i][j] += a[i] * f[j];
                    uc[i][j] += a[i] * g[j];
                }
        }
    }

    #pragma unroll
    for (int i = 0; i < 4; ++i) {
        int m = bm + m0 + i;
        float of[4], oc[4];
        #pragma unroll
        for (int j = 0; j < 4; ++j) {
            of[j] = uf[i][j] + b_fx[bn + n0 + j] + b_fh[bn + n0 + j];
            oc[j] = uc[i][j] + b_cx[bn + n0 + j] + b_ch[bn + n0 + j];
        }
        *reinterpret_cast<float4*>(&g_fx[m * H_DIM + bn + n0]) = *reinterpret_cast<float4*>(of);
        *reinterpret_cast<float4*>(&g_cx[m * H_DIM + bn + n0]) = *reinterpret_cast<float4*>(oc);
    }
}

// ---------------------------------------------------------------------------
// PERSISTENT tensor-core recurrence: one launch, 96 CTAs (24x4), weights in
// smem ONCE, 96 timesteps inside the kernel with a grid barrier per step.
// Per step & CTA: 128M x 64N of U=hh@W_fh^T and V=hh@W_ch^T, K=256 in 4
// cp.async.cg double-buffered chunks; bf16x3 fp32 emulation
// (Ahi*Bhi + Ahi*Blo + Alo*Bhi, f32 accumulate); fused gate epilogue.
// ---------------------------------------------------------------------------
#define W_STRIDE 528                 // 264 bf16 per row
#define A_STRIDE 144                 // 72 bf16 per row
#define SW_SZ (64 * W_STRIDE)        // 33792 B per weight matrix
#define OFF_A (4 * SW_SZ)            // 135168
#define SA_SZ (128 * A_STRIDE)       // 18432 B per (buf, half)
#define SMEM_TOTAL (OFF_A + 4 * SA_SZ)   // 208896 B

__global__ __launch_bounds__(256, 1)
void lstm_persist(float* __restrict__ out)
{
    extern __shared__ __align__(16) char smem[];
    const u32 sbase = smem_to_u32(smem);

    const int tid = threadIdx.x;
    const int lane = tid & 31;
    const int wid = tid >> 5;
    const int bm = blockIdx.x * 128;
    const int bn = blockIdx.y * 64;
    const int wm = (wid & 3) * 32;
    const int wn = (wid >> 2) * 32;

    // ---- stage weights ONCE (.ca — read-only for whole kernel) ----
    {
        const __nv_bfloat16* wsrc[4] = {g_Wfhi, g_Wflo, g_Wchi, g_Wclo};
        #pragma unroll
        for (int mat = 0; mat < 4; ++mat) {
            #pragma unroll
            for (int i = 0; i < 8; ++i) {
                int idx = tid + 256 * i;
                int n = idx >> 5, k = (idx & 31) * 8;
                CP_ASYNC_CA(sbase + mat * SW_SZ + n * W_STRIDE + k * 2,
                            &wsrc[mat][(bn + n) * H_DIM + k]);
            }
        }
        CP_COMMIT();
    }

    // ldmatrix lane address components
    const int lr = (lane & 7) + 8 * ((lane >> 3) & 1);
    const int lk = 8 * (lane >> 4);
    const u32 aAddrBase = sbase + OFF_A + (wm + lr) * A_STRIDE + lk * 2;
    const u32 bRow = (wn + lr) * W_STRIDE + lk * 2;

    const int gid = lane >> 2;
    const int tig = lane & 3;

    #pragma unroll 1
    for (int t = 0; t < S_LEN; ++t) {
        const __nv_bfloat16* __restrict__ hin_hi = g_hhi[t & 1];
        const __nv_bfloat16* __restrict__ hin_lo = g_hlo[t & 1];
        __nv_bfloat16* __restrict__ hout_hi = g_hhi[(t & 1) ^ 1];
        __nv_bfloat16* __restrict__ hout_lo = g_hlo[(t & 1) ^ 1];

        // ---- stage A chunks 0,1 (.cg: hh written by other CTAs last step) ----
        #pragma unroll
        for (int i = 0; i < 4; ++i) {
            int idx = tid + 256 * i;
            int row = idx >> 3, seg = idx & 7;
            CP_ASYNC_CG(sbase + OFF_A + 0 * SA_SZ + row * A_STRIDE + seg * 16,
                        &hin_hi[(bm + row) * H_DIM + seg * 8]);
            CP_ASYNC_CG(sbase + OFF_A + 1 * SA_SZ + row * A_STRIDE + seg * 16,
                        &hin_lo[(bm + row) * H_DIM + seg * 8]);
        }
        CP_COMMIT();
        #pragma unroll
        for (int i = 0; i < 4; ++i) {
            int idx = tid + 256 * i;
            int row = idx >> 3, seg = idx & 7;
            CP_ASYNC_CG(sbase + OFF_A + 2 * SA_SZ + row * A_STRIDE + seg * 16,
                        &hin_hi[(bm + row) * H_DIM + 64 + seg * 8]);
            CP_ASYNC_CG(sbase + OFF_A + 3 * SA_SZ + row * A_STRIDE + seg * 16,
                        &hin_lo[(bm + row) * H_DIM + 64 + seg * 8]);
        }
        CP_COMMIT();

        float u[2][4][4] = {};
        float v[2][4][4] = {};

        #pragma unroll 1
        for (int c = 0; c < 4; ++c) {
            const int buf = c & 1;
            if (c < 3) CP_WAIT(1); else CP_WAIT(0);
            __syncthreads();

            const u32 aHi = aAddrBase + (buf * 2 + 0) * SA_SZ;
            const u32 aLo = aAddrBase + (buf * 2 + 1) * SA_SZ;
            const u32 kByteW = (c * 64) * 2;

            #pragma unroll
            for (int ks = 0; ks < 4; ++ks) {
                u32 ahi[2][4], alo[2][4];
                #pragma unroll
                for (int mi = 0; mi < 2; ++mi) {
                    ldsm_x4(ahi[mi][0], ahi[mi][1], ahi[mi][2], ahi[mi][3],
                            aHi + mi * 16 * A_STRIDE + ks * 32);
                    ldsm_x4(alo[mi][0], alo[mi][1], alo[mi][2], alo[mi][3],
                            aLo + mi * 16 * A_STRIDE + ks * 32);
                }
                u32 bf_h[4][2], bf_l[4][2], bc_h[4][2], bc_l[4][2];
                #pragma unroll
                for (int nh = 0; nh < 2; ++nh) {
                    u32 off = bRow + nh * 16 * W_STRIDE + kByteW + ks * 32;
                    u32 r0, r1, r2, r3;
                    ldsm_x4(r0, r1, r2, r3, sbase + 0 * SW_SZ + off);
                    bf_h[nh*2][0] = r0; bf_h[nh*2][1] = r2; bf_h[nh*2+1][0] = r1; bf_h[nh*2+1][1] = r3;
                    ldsm_x4(r0, r1, r2, r3, sbase + 1 * SW_SZ + off);
                    bf_l[nh*2][0] = r0; bf_l[nh*2][1] = r2; bf_l[nh*2+1][0] = r1; bf_l[nh*2+1][1] = r3;
                    ldsm_x4(r0, r1, r2, r3, sbase + 2 * SW_SZ + off);
                    bc_h[nh*2][0] = r0; bc_h[nh*2][1] = r2; bc_h[nh*2+1][0] = r1; bc_h[nh*2+1][1] = r3;
                    ldsm_x4(r0, r1, r2, r3, sbase + 3 * SW_SZ + off);
                    bc_l[nh*2][0] = r0; bc_l[nh*2][1] = r2; bc_l[nh*2+1][0] = r1; bc_l[nh*2+1][1] = r3;
                }
                #pragma unroll
                for (int mi = 0; mi < 2; ++mi)
                    #pragma unroll
                    for (int nj = 0; nj < 4; ++nj) {
                        mma_bf16(u[mi][nj], ahi[mi], bf_h[nj]);
                        mma_bf16(u[mi][nj], ahi[mi], bf_l[nj]);
                        mma_bf16(u[mi][nj], alo[mi], bf_h[nj]);
                        mma_bf16(v[mi][nj], ahi[mi], bc_h[nj]);
                        mma_bf16(v[mi][nj], ahi[mi], bc_l[nj]);
                        mma_bf16(v[mi][nj], alo[mi], bc_h[nj]);
                    }
            }

            __syncthreads();
            if (c + 2 <= 3) {
                const int kc = (c + 2) * 64;
                #pragma unroll
                for (int i = 0; i < 4; ++i) {
                    int idx = tid + 256 * i;
                    int row = idx >> 3, seg = idx & 7;
                    CP_ASYNC_CG(sbase + OFF_A + (buf * 2 + 0) * SA_SZ + row * A_STRIDE + seg * 16,
                                &hin_hi[(bm + row) * H_DIM + kc + seg * 8]);
                    CP_ASYNC_CG(sbase + OFF_A + (buf * 2 + 1) * SA_SZ + row * A_STRIDE + seg * 16,
                                &hin_lo[(bm + row) * H_DIM + kc + seg * 8]);
                }
                CP_COMMIT();
            }
        }

        // ---- fused gate epilogue ----
        float* hseq = out + (size_t)t * NELEM;
        const int last = (t == S_LEN - 1);

        #pragma unroll
        for (int mi = 0; mi < 2; ++mi) {
            #pragma unroll
            for (int half = 0; half < 2; ++half) {
                const int r = bm + wm + mi * 16 + gid + half * 8;
                const int bb = r & (B_SZ - 1);
                #pragma unroll
                for (int nj = 0; nj < 4; ++nj) {
                    const int col = bn + wn + nj * 8 + 2 * tig;
                    const int off = r * H_DIM + col;

                    float u0 = u[mi][nj][half * 2 + 0], u1 = u[mi][nj][half * 2 + 1];
                    float v0 = v[mi][nj][half * 2 + 0], v1 = v[mi][nj][half * 2 + 1];

                    float2 fx2 = *reinterpret_cast<const float2*>(&g_fx[(t * B_SZ + bb) * H_DIM + col]);
                    float2 cx2 = *reinterpret_cast<const float2*>(&g_cx[off]);
                    float2 cc2 = *reinterpret_cast<const float2*>(&g_cc[off]);

                    float g0 = fast_sigmoid(fx2.x + u0);
                    float g1 = fast_sigmoid(fx2.y + u1);
                    float d0 = fast_tanh(cx2.x + v0);
                    float d1 = fast_tanh(cx2.y + v1);
                    float c0 = g0 * (cc2.x + d0);        // forget==input gate (ref bug)
                    float c1 = g1 * (cc2.y + d1);
                    float h0 = g0 * fast_tanh(c0);       // output gate == g (ref bug)
                    float h1 = g1 * fast_tanh(c1);

                    *reinterpret_cast<float2*>(&g_cc[off]) = make_float2(c0, c1);
                    *reinterpret_cast<float2*>(&hseq[off]) = make_float2(h0, h1);

                    __nv_bfloat16 h0h = __float2bfloat16(h0);
                    __nv_bfloat16 h1h = __float2bfloat16(h1);
                    __nv_bfloat162 hi2, lo2;
                    hi2.x = h0h; hi2.y = h1h;
                    lo2.x = __float2bfloat16(h0 - __bfloat162float(h0h));
                    lo2.y = __float2bfloat16(h1 - __bfloat162float(h1h));
                    *reinterpret_cast<__nv_bfloat162*>(&hout_hi[off]) = hi2;
                    *reinterpret_cast<__nv_bfloat162*>(&hout_lo[off]) = lo2;

                    if (last) {
                        *reinterpret_cast<float2*>(&out[(size_t)S_LEN * NELEM + off])       = make_float2(h0, h1);
                        *reinterpret_cast<float2*>(&out[(size_t)(S_LEN + 1) * NELEM + off]) = make_float2(c0, c1);
                    }
                }
            }
        }

        // ---- grid barrier (skip after last step) ----
        if (t < S_LEN - 1) {
            __threadfence();          // make hout stores visible (L2)
            __syncthreads();          // all threads of CTA fenced
            if (tid == 0) {
                atomicAdd(&g_bar, 1u);
                const unsigned goal = (unsigned)NCTA * (unsigned)(t + 1);
                while (*((volatile unsigned*)&g_bar) < goal) {
                    __nanosleep(64);
                }
            }
            __syncthreads();
            __threadfence();          // acquire side
        }
    }
}

// ---------------------------------------------------------------------------
// Launch: init -> weight split -> input projections -> ONE persistent kernel.
// Inputs: x, W_fx, b_fx, W_fh, b_fh, W_cx, b_cx, W_ch, b_ch
// Output: [h_seq (S,S,B,H) | h_fin (S,B,H) | c_fin (S,B,H)]
// ---------------------------------------------------------------------------
extern "C" void kernel_launch(void* const* d_in, const int* in_sizes, int n_in,
                              void* d_out, int out_size)
{
    const float* x    = (const float*)d_in[0];
    const float* W_fx = (const float*)d_in[1];
    const float* b_fx = (const float*)d_in[2];
    const float* W_fh = (const float*)d_in[3];
    const float* b_fh = (const float*)d_in[4];
    const float* W_cx = (const float*)d_in[5];
    const float* b_cx = (const float*)d_in[6];
    const float* W_ch = (const float*)d_in[7];
    const float* b_ch = (const float*)d_in[8];
    float* out = (float*)d_out;

    cudaFuncSetAttribute(lstm_persist, cudaFuncAttributeMaxDynamicSharedMemorySize, SMEM_TOTAL);

    zero_kernel<<<(NELEM / 4 + 255) / 256, 256>>>();
    splitw_kernel<<<(H_DIM * H_DIM + 255) / 256, 256>>>(W_fh, W_ch);
    pre_kernel<<<dim3(M_ALL / 64, H_DIM / 64), 256>>>(x, W_fx, b_fx, W_cx, b_cx, b_fh, b_ch);

    dim3 grid(M_ALL / 128, H_DIM / 64);   // 24 x 4 = 96 CTAs, all co-resident
    lstm_persist<<<grid, 256, SMEM_TOTAL>>>(out);
}